// round 12
// baseline (speedup 1.0000x reference)
#include <cuda_runtime.h>

#define B    16
#define C    32
#define T    16384
#define NL   30
#define OFF  3069
#define TOUT (T - OFF)   // 13315
#define NCH  256
#define LT   128         // layer time tile
#define BKK  16          // GEMM k-tile
#define GST  68          // smem row stride for 64-wide GEMM tiles (+4 pad)

typedef unsigned long long u64;

// Packed f32x2 helpers (Blackwell): 2 fp32 FMAs per issue slot, .rn rounding
#define PACK2(dst, lo, hi) \
    asm("mov.b64 %0, {%1, %2};" : "=l"(dst) : "f"(lo), "f"(hi))
#define UNPACK2(lo, hi, src) \
    asm("mov.b64 {%0, %1}, %2;" : "=f"(lo), "=f"(hi) : "l"(src))
#define FMA2(acc, a, b) \
    asm("fma.rn.f32x2 %0, %1, %2, %0;" : "+l"(acc) : "l"(a), "l"(b))

__device__ __forceinline__ unsigned f2tf32(float v) {
    unsigned r;
    asm("cvt.rna.tf32.f32 %0, %1;" : "=r"(r) : "f"(v));
    return r;
}
__device__ __forceinline__ void mma_tf32(
    float& c0, float& c1, float& c2, float& c3,
    unsigned a0, unsigned a1, unsigned a2, unsigned a3,
    unsigned b0, unsigned b1) {
    asm volatile(
        "mma.sync.aligned.m16n8k8.row.col.f32.tf32.tf32.f32 "
        "{%0,%1,%2,%3}, {%4,%5,%6,%7}, {%8,%9}, {%0,%1,%2,%3};"
        : "+f"(c0), "+f"(c1), "+f"(c2), "+f"(c3)
        : "r"(a0), "r"(a1), "r"(a2), "r"(a3), "r"(b0), "r"(b1));
}

// Scratch (device globals). CRITICAL RULE (learned R3-R11): these symbols must
// NEVER be passed as kernel launch arguments from host code — host-side &sym is
// a host shadow address and dereferencing it on-device triggers HMM migration
// (512MB device-mem delta -> harness rule trip). Reference them ONLY inside
// device code.
__device__ float g_x[2][(size_t)B * C * T];          //  64 MB ping-pong residual stream
__device__ float g_h[(size_t)NL * B * C * T];        // ~1  GB gated outputs; front 218MB
                                                     //   REUSED as head-hidden after skip GEMM
__device__ float g_skip[(size_t)B * NCH * TOUT];     // 218 MB relu(skip-sum)
__device__ float g_swT[(size_t)NL * C * NCH];        // skip_w transposed [l*C+c][co]
__device__ float g_w1T[(size_t)NCH * NCH];           // end1_w transposed [k][co]
__device__ float g_w2T[(size_t)NCH * NCH];           // end2_w transposed [k][co]

__device__ __forceinline__ float fast_tanh(float x) {
    return 1.f - 2.f / (__expf(2.f * x) + 1.f);
}
__device__ __forceinline__ float fast_sig(float x) {
    return 1.f / (1.f + __expf(-x));
}

// ---------------------------------------------------------------------------
// Weight transposes (one-shot, trivial)
// ---------------------------------------------------------------------------
__global__ void transpose_sw_kernel(const float* __restrict__ sw) {
    int idx = blockIdx.x * 256 + threadIdx.x;        // over NL*NCH*C, sw[l][co][c]
    if (idx >= NL * NCH * C) return;
    int c  = idx & 31;
    int co = (idx >> 5) & 255;
    int l  = idx >> 13;
    g_swT[((size_t)l * C + c) * NCH + co] = sw[idx];
}

__global__ void transpose_w_kernel(const float* __restrict__ w, int which) {
    int idx = blockIdx.x * 256 + threadIdx.x;        // over NCH*NCH, w[co][k]
    if (idx >= NCH * NCH) return;
    int k  = idx & 255;
    int co = idx >> 8;
    float* dst = which ? g_w2T : g_w1T;
    dst[(size_t)k * NCH + co] = w[idx];
}

// ---------------------------------------------------------------------------
// 1x1 causal conv: x0[b][c][t] = cw[c]*y[b][t] + cb[c]
// ---------------------------------------------------------------------------
__global__ void causal_kernel(const float* __restrict__ y,
                              const float* __restrict__ cw,
                              const float* __restrict__ cb) {
    int idx = blockIdx.x * 256 + threadIdx.x;         // over B*C*T
    if (idx >= B * C * T) return;
    int t = idx & (T - 1);
    int c = (idx >> 14) & 31;
    int b = idx >> 19;
    g_x[0][idx] = cw[c] * y[b * T + t] + cb[c];
}

// ---------------------------------------------------------------------------
// One WaveNet layer, 128-t tile, 256 threads (R8-proven, unchanged).
// ---------------------------------------------------------------------------
__global__ __launch_bounds__(256) void layer_kernel(
    const float* __restrict__ fw, const float* __restrict__ gw,
    const float* __restrict__ rw, int layer, int ping, int d, int lo) {
    extern __shared__ float sm[];
    float* s_fw = sm;                                 // 2048
    float* s_gw = sm + 2048;                          // 2048
    float* s_rw = sm + 4096;                          // 1024
    float* xs   = sm + 5120;                          // C*LT
    float* xd   = xs + C * LT;                        // C*LT
    float* hs   = xd + C * LT;                        // C*LT

    const float* xin  = g_x[ping];
    float*       xout = g_x[ping ^ 1];
    float*       hout = g_h + (size_t)layer * B * C * T;

    int b   = blockIdx.y;
    int tid = threadIdx.x;
    int t0  = (lo & ~(LT - 1)) + blockIdx.x * LT;     // 128-aligned tile start

    for (int i = tid; i < C * C * 2; i += 256) { s_fw[i] = fw[i]; s_gw[i] = gw[i]; }
    for (int i = tid; i < C * C;     i += 256) s_rw[i] = rw[i];

    const float* xb = xin + (size_t)b * C * T;
    for (int i = tid; i < C * LT; i += 256) {
        int c = i >> 7, tt = i & (LT - 1);
        int t = t0 + tt;
        bool v = (t >= lo) && (t < T);
        xs[i] = v ? xb[c * T + t]     : 0.f;
        xd[i] = v ? xb[c * T + t - d] : 0.f;
    }
    __syncthreads();

    // ---- phase 1: thread = (channels c0,c1) x (8 time steps), packed f32x2
    int cp  = tid >> 4;                               // 0..15
    int c0  = cp * 2, c1 = c0 + 1;
    int ttb = (tid & 15) * 8;
    u64 a_f0[4], a_g0[4], a_f1[4], a_g1[4];
#pragma unroll
    for (int q = 0; q < 4; q++) { a_f0[q]=0; a_g0[q]=0; a_f1[q]=0; a_g1[q]=0; }
#pragma unroll 8
    for (int ci = 0; ci < C; ci++) {
        float2 wf0 = *(const float2*)&s_fw[(c0 * C + ci) * 2];
        float2 wf1 = *(const float2*)&s_fw[(c1 * C + ci) * 2];
        float2 wg0 = *(const float2*)&s_gw[(c0 * C + ci) * 2];
        float2 wg1 = *(const float2*)&s_gw[(c1 * C + ci) * 2];
        u64 wf0x, wf0y, wg0x, wg0y, wf1x, wf1y, wg1x, wg1y;
        PACK2(wf0x, wf0.x, wf0.x);  PACK2(wf0y, wf0.y, wf0.y);
        PACK2(wg0x, wg0.x, wg0.x);  PACK2(wg0y, wg0.y, wg0.y);
        PACK2(wf1x, wf1.x, wf1.x);  PACK2(wf1y, wf1.y, wf1.y);
        PACK2(wg1x, wg1.x, wg1.x);  PACK2(wg1y, wg1.y, wg1.y);
        const u64* dp = (const u64*)&xd[ci * LT + ttb];
        const u64* sp = (const u64*)&xs[ci * LT + ttb];
#pragma unroll
        for (int q = 0; q < 4; q++) {
            u64 dv = dp[q], sv = sp[q];
            FMA2(a_f0[q], wf0x, dv);  FMA2(a_f0[q], wf0y, sv);
            FMA2(a_g0[q], wg0x, dv);  FMA2(a_g0[q], wg0y, sv);
            FMA2(a_f1[q], wf1x, dv);  FMA2(a_f1[q], wf1y, sv);
            FMA2(a_g1[q], wg1x, dv);  FMA2(a_g1[q], wg1y, sv);
        }
    }
    float af0[8], ag0[8], af1[8], ag1[8];
#pragma unroll
    for (int q = 0; q < 4; q++) {
        UNPACK2(af0[2*q], af0[2*q+1], a_f0[q]);
        UNPACK2(ag0[2*q], ag0[2*q+1], a_g0[q]);
        UNPACK2(af1[2*q], af1[2*q+1], a_f1[q]);
        UNPACK2(ag1[2*q], ag1[2*q+1], a_g1[q]);
    }
    float hv0[8], hv1[8];
#pragma unroll
    for (int q = 0; q < 8; q++) {
        hv0[q] = fast_tanh(af0[q]) * fast_sig(ag0[q]);
        hv1[q] = fast_tanh(af1[q]) * fast_sig(ag1[q]);
    }
#pragma unroll
    for (int q = 0; q < 8; q++) {
        hs[c0 * LT + ttb + q] = hv0[q];
        hs[c1 * LT + ttb + q] = hv1[q];
    }
    {
        // global h store only where skip reads it (t >= OFF)
        float* h0 = hout + (size_t)b * C * T + (size_t)c0 * T;
        float* h1 = hout + (size_t)b * C * T + (size_t)c1 * T;
#pragma unroll
        for (int q = 0; q < 8; q++) {
            int t = t0 + ttb + q;
            if (t >= OFF && t < T) { h0[t] = hv0[q]; h1[t] = hv1[q]; }
        }
    }
    __syncthreads();

    // ---- phase 2: residual 1x1 conv; thread = (group of 16 out-ch, 1 t)
    {
        int grp = tid >> 7, tloc = tid & (LT - 1);
        float hreg[C];
#pragma unroll
        for (int ci = 0; ci < C; ci++) hreg[ci] = hs[ci * LT + tloc];
        int tg = t0 + tloc;
        if (tg >= lo && tg < T) {
            float* xob = xout + (size_t)b * C * T;
#pragma unroll
            for (int k = 0; k < 16; k++) {
                int co = grp * 16 + k;
                float acc = 0.f;
#pragma unroll
                for (int ci = 0; ci < C; ci++) acc += s_rw[co * C + ci] * hreg[ci];
                xob[co * T + tg] = acc + xs[co * LT + tloc];
            }
        }
    }
}

// ---------------------------------------------------------------------------
// Tensor-core GEMM (3xTF32 split), BM=64/BN=64/BK=16, 8 warps = 2(M) x 4(N),
// warp tile 32x16 via m16n8k8; 16 fp32 accumulators/thread.
// ALL global-scratch pointers resolved INSIDE the kernel from `mode`:
//   mode 0: A=g_swT (k=960), B=g_h rows (stride T, base OFF), relu      -> g_skip
//   mode 1: A=g_w1T (k=256), B=g_skip (stride TOUT), relu(v+bias)       -> g_h (hid)
//   mode 2: A=g_w2T (k=256), B=g_h hid (stride TOUT), v+bias            -> out (arg)
// ---------------------------------------------------------------------------
__global__ __launch_bounds__(256, 1) void mma_gemm_kernel(
    const float* __restrict__ bias, float* __restrict__ out,
    int kdim, int mode) {
    __shared__ float sAh[BKK * GST], sAl[BKK * GST];  // [k][m], 64 wide
    __shared__ float sBh[BKK * GST], sBl[BKK * GST];  // [k][j], 64 wide

    const float* wT = (mode == 0) ? g_swT : (mode == 1) ? g_w1T : g_w2T;
    float* dst      = (mode == 0) ? g_skip : (mode == 1) ? g_h : out;

    int b    = blockIdx.z;
    int mb   = blockIdx.y * 64;
    int j0   = blockIdx.x * 64;
    int tid  = threadIdx.x;
    int wid  = tid >> 5, lane = tid & 31;
    int wm   = (wid >> 2) * 32;                       // warp M offset (0/32)
    int wn   = (wid & 3) * 16;                        // warp N offset (0/16/32/48)
    int g    = lane >> 2;                             // groupID 0..7
    int tg   = lane & 3;                              // threadID in group

    float cacc[2][2][4];                              // [mt][nt][frag]
#pragma unroll
    for (int mt = 0; mt < 2; mt++)
#pragma unroll
        for (int nt = 0; nt < 2; nt++)
#pragma unroll
            for (int q = 0; q < 4; q++) cacc[mt][nt][q] = 0.f;

    int krow = tid >> 4;                              // 0..15
    int e4   = (tid & 15) * 4;                        // 0..60

    for (int k0 = 0; k0 < kdim; k0 += BKK) {
        // A tile fill: wT[k][co], coalesced over co; split hi/lo
        {
            const float* ap = wT + (size_t)(k0 + krow) * NCH + mb + e4;
#pragma unroll
            for (int q = 0; q < 4; q++) {
                float v = __ldg(ap + q);
                unsigned h = f2tf32(v);
                sAh[krow * GST + e4 + q] = __uint_as_float(h);
                sAl[krow * GST + e4 + q] =
                    __uint_as_float(f2tf32(v - __uint_as_float(h)));
            }
        }
        // B tile fill
        {
            int k = k0 + krow;
            const float* hrow;
            if (mode == 0)
                hrow = g_h + (((size_t)(k >> 5) * B + b) * C + (k & 31)) * T + OFF;
            else if (mode == 1)
                hrow = g_skip + ((size_t)b * NCH + k) * TOUT;
            else
                hrow = g_h + ((size_t)b * NCH + k) * TOUT;
#pragma unroll
            for (int q = 0; q < 4; q++) {
                int j = j0 + e4 + q;
                float v = (j < TOUT) ? __ldg(hrow + j) : 0.f;
                unsigned h = f2tf32(v);
                sBh[krow * GST + e4 + q] = __uint_as_float(h);
                sBl[krow * GST + e4 + q] =
                    __uint_as_float(f2tf32(v - __uint_as_float(h)));
            }
        }
        __syncthreads();

#pragma unroll
        for (int k2 = 0; k2 < 2; k2++) {
            int ak = k2 * 8 + tg;
#pragma unroll
            for (int nt = 0; nt < 2; nt++) {
                int bn = wn + nt * 8 + g;
                unsigned bh0 = __float_as_uint(sBh[ak * GST + bn]);
                unsigned bh1 = __float_as_uint(sBh[(ak + 4) * GST + bn]);
                unsigned bl0 = __float_as_uint(sBl[ak * GST + bn]);
                unsigned bl1 = __float_as_uint(sBl[(ak + 4) * GST + bn]);
#pragma unroll
                for (int mt = 0; mt < 2; mt++) {
                    int am = wm + mt * 16 + g;
                    unsigned ah0 = __float_as_uint(sAh[ak * GST + am]);
                    unsigned ah1 = __float_as_uint(sAh[ak * GST + am + 8]);
                    unsigned ah2 = __float_as_uint(sAh[(ak + 4) * GST + am]);
                    unsigned ah3 = __float_as_uint(sAh[(ak + 4) * GST + am + 8]);
                    unsigned al0 = __float_as_uint(sAl[ak * GST + am]);
                    unsigned al1 = __float_as_uint(sAl[ak * GST + am + 8]);
                    unsigned al2 = __float_as_uint(sAl[(ak + 4) * GST + am]);
                    unsigned al3 = __float_as_uint(sAl[(ak + 4) * GST + am + 8]);
                    mma_tf32(cacc[mt][nt][0], cacc[mt][nt][1],
                             cacc[mt][nt][2], cacc[mt][nt][3],
                             ah0, ah1, ah2, ah3, bh0, bh1);
                    mma_tf32(cacc[mt][nt][0], cacc[mt][nt][1],
                             cacc[mt][nt][2], cacc[mt][nt][3],
                             ah0, ah1, ah2, ah3, bl0, bl1);
                    mma_tf32(cacc[mt][nt][0], cacc[mt][nt][1],
                             cacc[mt][nt][2], cacc[mt][nt][3],
                             al0, al1, al2, al3, bh0, bh1);
                }
            }
        }
        __syncthreads();
    }

    // epilogue: C frag rows g, g+8; cols 2tg, 2tg+1
#pragma unroll
    for (int mt = 0; mt < 2; mt++) {
        int r0 = mb + wm + mt * 16 + g;
        int r1 = r0 + 8;
        float bv0 = 0.f, bv1 = 0.f;
        if (mode != 0) { bv0 = bias[r0]; bv1 = bias[r1]; }
        float* d0 = dst + ((size_t)b * NCH + r0) * TOUT;
        float* d1 = dst + ((size_t)b * NCH + r1) * TOUT;
#pragma unroll
        for (int nt = 0; nt < 2; nt++) {
            int j = j0 + wn + nt * 8 + tg * 2;
            float v0 = cacc[mt][nt][0] + bv0;
            float v1 = cacc[mt][nt][1] + bv0;
            float v2 = cacc[mt][nt][2] + bv1;
            float v3 = cacc[mt][nt][3] + bv1;
            if (mode != 2) {
                v0 = fmaxf(v0, 0.f);  v1 = fmaxf(v1, 0.f);
                v2 = fmaxf(v2, 0.f);  v3 = fmaxf(v3, 0.f);
            }
            if (j < TOUT)     { d0[j] = v0;     d1[j] = v2; }
            if (j + 1 < TOUT) { d0[j + 1] = v1; d1[j + 1] = v3; }
        }
    }
}

// ---------------------------------------------------------------------------
extern "C" void kernel_launch(void* const* d_in, const int* in_sizes, int n_in,
                              void* d_out, int out_size) {
    const float* y   = (const float*)d_in[0];
    const float* cw  = (const float*)d_in[1];
    const float* cb  = (const float*)d_in[2];
    const float* fw  = (const float*)d_in[3];
    const float* gw  = (const float*)d_in[4];
    const float* rw  = (const float*)d_in[5];
    const float* sw  = (const float*)d_in[6];
    const float* e1w = (const float*)d_in[7];
    const float* e1b = (const float*)d_in[8];
    const float* e2w = (const float*)d_in[9];
    const float* e2b = (const float*)d_in[10];
    float* out = (float*)d_out;

    transpose_sw_kernel<<<(NL * NCH * C + 255) / 256, 256>>>(sw);
    transpose_w_kernel<<<(NCH * NCH + 255) / 256, 256>>>(e1w, 0);
    transpose_w_kernel<<<(NCH * NCH + 255) / 256, 256>>>(e2w, 1);

    causal_kernel<<<(B * C * T + 255) / 256, 256>>>(y, cw, cb);

    const int lyr_smem = (5120 + 3 * C * LT) * 4;     // 69,632 B
    cudaFuncSetAttribute(layer_kernel, cudaFuncAttributeMaxDynamicSharedMemorySize,
                         lyr_smem);

    int lin = 0;
    for (int i = 0; i < NL; i++) {
        int d  = 1 << (i % 10);
        int lo = lin + d;                  // first valid output time index
        int tb = lo & ~(LT - 1);
        int tiles = (T - tb + LT - 1) / LT;
        dim3 grid(tiles, B);
        layer_kernel<<<grid, 256, lyr_smem>>>(fw + (size_t)i * C * C * 2,
                                              gw + (size_t)i * C * C * 2,
                                              rw + (size_t)i * C * C,
                                              i, i & 1, d, lo);
        lin = lo;
    }

    // NOTE: only harness pointers (e1b/e2b/out) are passed; all scratch
    // globals are resolved inside the kernel (see comment at globals).
    dim3 gg((TOUT + 63) / 64, NCH / 64, B);           // (209, 4, 16)
    mma_gemm_kernel<<<gg, 256>>>(nullptr, nullptr, NL * C, 0);
    mma_gemm_kernel<<<gg, 256>>>(e1b, nullptr, NCH, 1);
    mma_gemm_kernel<<<gg, 256>>>(e2b, out, NCH, 2);
}

// round 13
// speedup vs baseline: 1.1010x; 1.1010x over previous
#include <cuda_runtime.h>

#define B    16
#define C    32
#define T    16384
#define NL   30
#define OFF  3069
#define TOUT (T - OFF)   // 13315
#define NCH  256
#define TT2  32
#define TT3  16
#define LT   128         // layer time tile

typedef unsigned long long u64;

// Packed f32x2 helpers (Blackwell): 2 fp32 FMAs per issue slot, .rn rounding
#define PACK2(dst, lo, hi) \
    asm("mov.b64 %0, {%1, %2};" : "=l"(dst) : "f"(lo), "f"(hi))
#define UNPACK2(lo, hi, src) \
    asm("mov.b64 {%0, %1}, %2;" : "=f"(lo), "=f"(hi) : "l"(src))
#define FMA2(acc, a, b) \
    asm("fma.rn.f32x2 %0, %1, %2, %0;" : "+l"(acc) : "l"(a), "l"(b))

// HW tanh (MUFU.TANH, 1 instruction). sig(g) = 0.5*(1+tanh(g/2)).
__device__ __forceinline__ float tanh_hw(float x) {
    float r;
    asm("tanh.approx.f32 %0, %1;" : "=f"(r) : "f"(x));
    return r;
}
__device__ __forceinline__ float gate_hw(float f, float g) {
    return tanh_hw(f) * (0.5f * tanh_hw(0.5f * g) + 0.5f);
}

// Scratch (device globals). CRITICAL RULE (learned R3-R12): these symbols must
// NEVER be passed as kernel launch arguments from host code — host-side &sym is
// a host shadow address; on-device deref triggers HMM migration (512MB device
// mem delta -> harness rule trip). Reference them ONLY inside device code.
__device__ float g_x[2][(size_t)B * C * T];          //  64 MB ping-pong residual stream
__device__ float g_h[(size_t)NL * B * C * T];        // ~1  GB per-layer gated outputs
__device__ float g_skip[(size_t)B * NCH * TOUT];     // 218 MB relu(skip-sum)
__device__ float g_swT[(size_t)NL * C * NCH];        // skip_w transposed [l*C+c][co]
__device__ float g_w1T[(size_t)NCH * NCH];           // end1_w transposed [k][co]
__device__ float g_w2T[(size_t)NCH * NCH];           // end2_w transposed [k][co]

// ---------------------------------------------------------------------------
// Weight transposes (one-shot, trivial)
// ---------------------------------------------------------------------------
__global__ void transpose_sw_kernel(const float* __restrict__ sw) {
    int idx = blockIdx.x * 256 + threadIdx.x;        // over NL*NCH*C, sw[l][co][c]
    if (idx >= NL * NCH * C) return;
    int c  = idx & 31;
    int co = (idx >> 5) & 255;
    int l  = idx >> 13;
    g_swT[((size_t)l * C + c) * NCH + co] = sw[idx];
}

__global__ void transpose_w_kernel(const float* __restrict__ w, int which) {
    int idx = blockIdx.x * 256 + threadIdx.x;        // over NCH*NCH, w[co][k]
    if (idx >= NCH * NCH) return;
    int k  = idx & 255;
    int co = idx >> 8;
    float* dst = which ? g_w2T : g_w1T;
    dst[(size_t)k * NCH + co] = w[idx];
}

// ---------------------------------------------------------------------------
// 1x1 causal conv: x0[b][c][t] = cw[c]*y[b][t] + cb[c]
// ---------------------------------------------------------------------------
__global__ void causal_kernel(const float* __restrict__ y,
                              const float* __restrict__ cw,
                              const float* __restrict__ cb) {
    int idx = blockIdx.x * 256 + threadIdx.x;         // over B*C*T
    if (idx >= B * C * T) return;
    int t = idx & (T - 1);
    int c = (idx >> 14) & 31;
    int b = idx >> 19;
    g_x[0][idx] = cw[c] * y[b * T + t] + cb[c];
}

// ---------------------------------------------------------------------------
// One WaveNet layer, 128-t tile, 256 threads.
// Phase 1: thread = (2 out-ch, 8 t), f32x2-packed FMAs, MUFU.TANH gating.
// Phase 2: thread = (16 out-ch, 1 t), scalar.
// ---------------------------------------------------------------------------
__global__ __launch_bounds__(256) void layer_kernel(
    const float* __restrict__ fw, const float* __restrict__ gw,
    const float* __restrict__ rw, int layer, int ping, int d, int lo) {
    extern __shared__ float sm[];
    float* s_fw = sm;                                 // 2048
    float* s_gw = sm + 2048;                          // 2048
    float* s_rw = sm + 4096;                          // 1024
    float* xs   = sm + 5120;                          // C*LT
    float* xd   = xs + C * LT;                        // C*LT
    float* hs   = xd + C * LT;                        // C*LT

    const float* xin  = g_x[ping];
    float*       xout = g_x[ping ^ 1];
    float*       hout = g_h + (size_t)layer * B * C * T;

    int b   = blockIdx.y;
    int tid = threadIdx.x;
    int t0  = (lo & ~(LT - 1)) + blockIdx.x * LT;     // 128-aligned tile start

    for (int i = tid; i < C * C * 2; i += 256) { s_fw[i] = fw[i]; s_gw[i] = gw[i]; }
    for (int i = tid; i < C * C;     i += 256) s_rw[i] = rw[i];

    const float* xb = xin + (size_t)b * C * T;
    for (int i = tid; i < C * LT; i += 256) {
        int c = i >> 7, tt = i & (LT - 1);
        int t = t0 + tt;
        bool v = (t >= lo) && (t < T);
        xs[i] = v ? xb[c * T + t]     : 0.f;
        xd[i] = v ? xb[c * T + t - d] : 0.f;
    }
    __syncthreads();

    // ---- phase 1: thread = (channels c0,c1) x (8 time steps), packed f32x2
    int cp  = tid >> 4;                               // 0..15
    int c0  = cp * 2, c1 = c0 + 1;
    int ttb = (tid & 15) * 8;
    u64 a_f0[4], a_g0[4], a_f1[4], a_g1[4];
#pragma unroll
    for (int q = 0; q < 4; q++) { a_f0[q]=0; a_g0[q]=0; a_f1[q]=0; a_g1[q]=0; }
#pragma unroll 8
    for (int ci = 0; ci < C; ci++) {
        float2 wf0 = *(const float2*)&s_fw[(c0 * C + ci) * 2];
        float2 wf1 = *(const float2*)&s_fw[(c1 * C + ci) * 2];
        float2 wg0 = *(const float2*)&s_gw[(c0 * C + ci) * 2];
        float2 wg1 = *(const float2*)&s_gw[(c1 * C + ci) * 2];
        u64 wf0x, wf0y, wg0x, wg0y, wf1x, wf1y, wg1x, wg1y;
        PACK2(wf0x, wf0.x, wf0.x);  PACK2(wf0y, wf0.y, wf0.y);
        PACK2(wg0x, wg0.x, wg0.x);  PACK2(wg0y, wg0.y, wg0.y);
        PACK2(wf1x, wf1.x, wf1.x);  PACK2(wf1y, wf1.y, wf1.y);
        PACK2(wg1x, wg1.x, wg1.x);  PACK2(wg1y, wg1.y, wg1.y);
        const u64* dp = (const u64*)&xd[ci * LT + ttb];
        const u64* sp = (const u64*)&xs[ci * LT + ttb];
#pragma unroll
        for (int q = 0; q < 4; q++) {
            u64 dv = dp[q], sv = sp[q];
            FMA2(a_f0[q], wf0x, dv);  FMA2(a_f0[q], wf0y, sv);
            FMA2(a_g0[q], wg0x, dv);  FMA2(a_g0[q], wg0y, sv);
            FMA2(a_f1[q], wf1x, dv);  FMA2(a_f1[q], wf1y, sv);
            FMA2(a_g1[q], wg1x, dv);  FMA2(a_g1[q], wg1y, sv);
        }
    }
    float af0[8], ag0[8], af1[8], ag1[8];
#pragma unroll
    for (int q = 0; q < 4; q++) {
        UNPACK2(af0[2*q], af0[2*q+1], a_f0[q]);
        UNPACK2(ag0[2*q], ag0[2*q+1], a_g0[q]);
        UNPACK2(af1[2*q], af1[2*q+1], a_f1[q]);
        UNPACK2(ag1[2*q], ag1[2*q+1], a_g1[q]);
    }
    float hv0[8], hv1[8];
#pragma unroll
    for (int q = 0; q < 8; q++) {
        hv0[q] = gate_hw(af0[q], ag0[q]);
        hv1[q] = gate_hw(af1[q], ag1[q]);
    }
#pragma unroll
    for (int q = 0; q < 8; q++) {
        hs[c0 * LT + ttb + q] = hv0[q];
        hs[c1 * LT + ttb + q] = hv1[q];
    }
    {
        // global h store only where skip reads it (t >= OFF)
        float* h0 = hout + (size_t)b * C * T + (size_t)c0 * T;
        float* h1 = hout + (size_t)b * C * T + (size_t)c1 * T;
#pragma unroll
        for (int q = 0; q < 8; q++) {
            int t = t0 + ttb + q;
            if (t >= OFF && t < T) { h0[t] = hv0[q]; h1[t] = hv1[q]; }
        }
    }
    __syncthreads();

    // ---- phase 2: residual 1x1 conv; thread = (group of 16 out-ch, 1 t)
    {
        int grp = tid >> 7, tloc = tid & (LT - 1);
        float hreg[C];
#pragma unroll
        for (int ci = 0; ci < C; ci++) hreg[ci] = hs[ci * LT + tloc];
        int tg = t0 + tloc;
        if (tg >= lo && tg < T) {
            float* xob = xout + (size_t)b * C * T;
#pragma unroll
            for (int k = 0; k < 16; k++) {
                int co = grp * 16 + k;
                float acc = 0.f;
#pragma unroll
                for (int ci = 0; ci < C; ci++) acc += s_rw[co * C + ci] * hreg[ci];
                xob[co * T + tg] = acc + xs[co * LT + tloc];
            }
        }
    }
}

// ---------------------------------------------------------------------------
// Fused skip reduction (coalesced g_swT weights), f32x2-packed (R8-proven).
// ---------------------------------------------------------------------------
__global__ __launch_bounds__(256) void skip_kernel() {
    extern __shared__ float hs2[];                    // [NL*C][TT2]
    int b = blockIdx.y, j0 = blockIdx.x * TT2, tid = threadIdx.x;

    for (int i = tid; i < NL * C * TT2; i += 256) {
        int k = i >> 5, tt = i & (TT2 - 1);
        int j = j0 + tt;
        float v = 0.f;
        if (j < TOUT) {
            int layer = k >> 5, cc = k & 31;
            v = g_h[(((size_t)layer * B + b) * C + cc) * T + OFF + j];
        }
        hs2[i] = v;
    }
    __syncthreads();

    int co = tid;
    u64 acc2[TT2 / 2];
#pragma unroll
    for (int q = 0; q < TT2 / 2; q++) acc2[q] = 0;

    const float* wT = g_swT + co;                     // lane-coalesced base
#pragma unroll 4
    for (int kk = 0; kk < NL * C; kk++) {             // kk = layer*C + c2
        float w = __ldg(&wT[(size_t)kk * NCH]);
        u64 w2;  PACK2(w2, w, w);
        const u64* hp = (const u64*)&hs2[kk * TT2];
#pragma unroll
        for (int q = 0; q < TT2 / 2; q++) FMA2(acc2[q], w2, hp[q]);
    }
    float* so = g_skip + ((size_t)b * NCH + co) * TOUT;
#pragma unroll
    for (int q = 0; q < TT2 / 2; q++) {
        float lo, hi;
        UNPACK2(lo, hi, acc2[q]);
        int j = j0 + 2 * q;
        if (j     < TOUT) so[j]     = fmaxf(lo, 0.f);
        if (j + 1 < TOUT) so[j + 1] = fmaxf(hi, 0.f);
    }
}

// ---------------------------------------------------------------------------
// Head (coalesced g_w1T/g_w2T), f32x2-packed (R8-proven).
// ---------------------------------------------------------------------------
__global__ __launch_bounds__(256) void head_kernel(
    const float* __restrict__ b1, const float* __restrict__ b2,
    float* __restrict__ out) {
    __shared__ float ss[NCH * TT3];                   // 16 KB relu(skip) tile
    __shared__ float as[NCH * TT3];                   // 16 KB hidden tile
    int b = blockIdx.y, j0 = blockIdx.x * TT3, tid = threadIdx.x;

    for (int i = tid; i < NCH * TT3; i += 256) {
        int k = i >> 4, tt = i & (TT3 - 1);
        int j = j0 + tt;
        ss[i] = (j < TOUT) ? g_skip[((size_t)b * NCH + k) * TOUT + j] : 0.f;
    }
    __syncthreads();

    int co = tid;
    u64 acc2[TT3 / 2];
#pragma unroll
    for (int q = 0; q < TT3 / 2; q++) acc2[q] = 0;
    const float* w1c = g_w1T + co;
#pragma unroll 4
    for (int k = 0; k < NCH; k++) {
        float w = __ldg(&w1c[(size_t)k * NCH]);
        u64 w2;  PACK2(w2, w, w);
        const u64* sp = (const u64*)&ss[k * TT3];
#pragma unroll
        for (int q = 0; q < TT3 / 2; q++) FMA2(acc2[q], w2, sp[q]);
    }
    float bb1 = b1[co];
#pragma unroll
    for (int q = 0; q < TT3 / 2; q++) {
        float lo, hi;
        UNPACK2(lo, hi, acc2[q]);
        as[co * TT3 + 2 * q]     = fmaxf(lo + bb1, 0.f);
        as[co * TT3 + 2 * q + 1] = fmaxf(hi + bb1, 0.f);
    }
    __syncthreads();

#pragma unroll
    for (int q = 0; q < TT3 / 2; q++) acc2[q] = 0;
    const float* w2c = g_w2T + co;
#pragma unroll 4
    for (int k = 0; k < NCH; k++) {
        float w = __ldg(&w2c[(size_t)k * NCH]);
        u64 w2;  PACK2(w2, w, w);
        const u64* sp = (const u64*)&as[k * TT3];
#pragma unroll
        for (int q = 0; q < TT3 / 2; q++) FMA2(acc2[q], w2, sp[q]);
    }
    float bb2 = b2[co];
    float* op = out + ((size_t)b * NCH + co) * TOUT;
#pragma unroll
    for (int q = 0; q < TT3 / 2; q++) {
        float lo, hi;
        UNPACK2(lo, hi, acc2[q]);
        int j = j0 + 2 * q;
        if (j     < TOUT) op[j]     = lo + bb2;
        if (j + 1 < TOUT) op[j + 1] = hi + bb2;
    }
}

// ---------------------------------------------------------------------------
extern "C" void kernel_launch(void* const* d_in, const int* in_sizes, int n_in,
                              void* d_out, int out_size) {
    const float* y   = (const float*)d_in[0];
    const float* cw  = (const float*)d_in[1];
    const float* cb  = (const float*)d_in[2];
    const float* fw  = (const float*)d_in[3];
    const float* gw  = (const float*)d_in[4];
    const float* rw  = (const float*)d_in[5];
    const float* sw  = (const float*)d_in[6];
    const float* e1w = (const float*)d_in[7];
    const float* e1b = (const float*)d_in[8];
    const float* e2w = (const float*)d_in[9];
    const float* e2b = (const float*)d_in[10];
    float* out = (float*)d_out;

    transpose_sw_kernel<<<(NL * NCH * C + 255) / 256, 256>>>(sw);
    transpose_w_kernel<<<(NCH * NCH + 255) / 256, 256>>>(e1w, 0);
    transpose_w_kernel<<<(NCH * NCH + 255) / 256, 256>>>(e2w, 1);

    causal_kernel<<<(B * C * T + 255) / 256, 256>>>(y, cw, cb);

    const int lyr_smem = (5120 + 3 * C * LT) * 4;     // 69,632 B
    cudaFuncSetAttribute(layer_kernel, cudaFuncAttributeMaxDynamicSharedMemorySize,
                         lyr_smem);

    int lin = 0;
    for (int i = 0; i < NL; i++) {
        int d  = 1 << (i % 10);
        int lo = lin + d;                  // first valid output time index
        int tb = lo & ~(LT - 1);
        int tiles = (T - tb + LT - 1) / LT;
        dim3 grid(tiles, B);
        layer_kernel<<<grid, 256, lyr_smem>>>(fw + (size_t)i * C * C * 2,
                                              gw + (size_t)i * C * C * 2,
                                              rw + (size_t)i * C * C,
                                              i, i & 1, d, lo);
        lin = lo;
    }

    cudaFuncSetAttribute(skip_kernel, cudaFuncAttributeMaxDynamicSharedMemorySize,
                         NL * C * TT2 * 4);
    dim3 gs((TOUT + TT2 - 1) / TT2, B);
    skip_kernel<<<gs, 256, NL * C * TT2 * 4>>>();

    dim3 gh((TOUT + TT3 - 1) / TT3, B);
    head_kernel<<<gh, 256>>>(e1b, e2b, out);
}

// round 14
// speedup vs baseline: 1.1605x; 1.0541x over previous
#include <cuda_runtime.h>

#define B    16
#define C    32
#define T    16384
#define NL   30
#define OFF  3069
#define TOUT (T - OFF)   // 13315
#define NCH  256
#define TT2  32
#define TT3  32
#define LT   128         // layer time tile

typedef unsigned long long u64;

// Packed f32x2 helpers (Blackwell): 2 fp32 FMAs per issue slot, .rn rounding
#define PACK2(dst, lo, hi) \
    asm("mov.b64 %0, {%1, %2};" : "=l"(dst) : "f"(lo), "f"(hi))
#define UNPACK2(lo, hi, src) \
    asm("mov.b64 {%0, %1}, %2;" : "=f"(lo), "=f"(hi) : "l"(src))
#define FMA2(acc, a, b) \
    asm("fma.rn.f32x2 %0, %1, %2, %0;" : "+l"(acc) : "l"(a), "l"(b))

// HW tanh (MUFU.TANH, 1 instruction). sig(g) = 0.5*(1+tanh(g/2)).
__device__ __forceinline__ float tanh_hw(float x) {
    float r;
    asm("tanh.approx.f32 %0, %1;" : "=f"(r) : "f"(x));
    return r;
}
__device__ __forceinline__ float gate_hw(float f, float g) {
    return tanh_hw(f) * (0.5f * tanh_hw(0.5f * g) + 0.5f);
}

// Scratch (device globals). CRITICAL RULE (learned R3-R12): these symbols must
// NEVER be passed as kernel launch arguments from host code — host-side &sym is
// a host shadow address; on-device deref triggers HMM migration (512MB device
// mem delta -> harness rule trip). Reference them ONLY inside device code.
__device__ float g_x[2][(size_t)B * C * T];          //  64 MB ping-pong residual stream
__device__ float g_h[(size_t)NL * B * C * T];        // ~1  GB per-layer gated outputs
__device__ float g_skip[(size_t)B * NCH * TOUT];     // 218 MB relu(skip-sum)
__device__ float g_swT[(size_t)NL * C * NCH];        // skip_w transposed [l*C+c][co]
__device__ float g_w1T[(size_t)NCH * NCH];           // end1_w transposed [k][co]
__device__ float g_w2T[(size_t)NCH * NCH];           // end2_w transposed [k][co]

// ---------------------------------------------------------------------------
// Weight transposes (one-shot, trivial)
// ---------------------------------------------------------------------------
__global__ void transpose_sw_kernel(const float* __restrict__ sw) {
    int idx = blockIdx.x * 256 + threadIdx.x;        // over NL*NCH*C, sw[l][co][c]
    if (idx >= NL * NCH * C) return;
    int c  = idx & 31;
    int co = (idx >> 5) & 255;
    int l  = idx >> 13;
    g_swT[((size_t)l * C + c) * NCH + co] = sw[idx];
}

__global__ void transpose_w_kernel(const float* __restrict__ w, int which) {
    int idx = blockIdx.x * 256 + threadIdx.x;        // over NCH*NCH, w[co][k]
    if (idx >= NCH * NCH) return;
    int k  = idx & 255;
    int co = idx >> 8;
    float* dst = which ? g_w2T : g_w1T;
    dst[(size_t)k * NCH + co] = w[idx];
}

// ---------------------------------------------------------------------------
// 1x1 causal conv: x0[b][c][t] = cw[c]*y[b][t] + cb[c]
// ---------------------------------------------------------------------------
__global__ void causal_kernel(const float* __restrict__ y,
                              const float* __restrict__ cw,
                              const float* __restrict__ cb) {
    int idx = blockIdx.x * 256 + threadIdx.x;         // over B*C*T
    if (idx >= B * C * T) return;
    int t = idx & (T - 1);
    int c = (idx >> 14) & 31;
    int b = idx >> 19;
    g_x[0][idx] = cw[c] * y[b * T + t] + cb[c];
}

// ---------------------------------------------------------------------------
// One WaveNet layer, 128-t tile, 256 threads.
// Phase 1: thread = (2 out-ch, 8 t), f32x2-packed FMAs, MUFU.TANH gating.
// Phase 2: thread = (16 out-ch, 1 t), scalar.
// ---------------------------------------------------------------------------
__global__ __launch_bounds__(256) void layer_kernel(
    const float* __restrict__ fw, const float* __restrict__ gw,
    const float* __restrict__ rw, int layer, int ping, int d, int lo) {
    extern __shared__ float sm[];
    float* s_fw = sm;                                 // 2048
    float* s_gw = sm + 2048;                          // 2048
    float* s_rw = sm + 4096;                          // 1024
    float* xs   = sm + 5120;                          // C*LT
    float* xd   = xs + C * LT;                        // C*LT
    float* hs   = xd + C * LT;                        // C*LT

    const float* xin  = g_x[ping];
    float*       xout = g_x[ping ^ 1];
    float*       hout = g_h + (size_t)layer * B * C * T;

    int b   = blockIdx.y;
    int tid = threadIdx.x;
    int t0  = (lo & ~(LT - 1)) + blockIdx.x * LT;     // 128-aligned; t0 <= T-128

    for (int i = tid; i < C * C * 2; i += 256) { s_fw[i] = fw[i]; s_gw[i] = gw[i]; }
    for (int i = tid; i < C * C;     i += 256) s_rw[i] = rw[i];

    const float* xb = xin + (size_t)b * C * T;
    for (int i = tid; i < C * LT; i += 256) {
        int c = i >> 7, tt = i & (LT - 1);
        int t = t0 + tt;
        bool v = (t >= lo);                           // t < T always (t0 <= T-128)
        xs[i] = v ? xb[c * T + t]     : 0.f;
        xd[i] = v ? xb[c * T + t - d] : 0.f;
    }
    __syncthreads();

    // ---- phase 1: thread = (channels c0,c1) x (8 time steps), packed f32x2
    int cp  = tid >> 4;                               // 0..15
    int c0  = cp * 2, c1 = c0 + 1;
    int ttb = (tid & 15) * 8;
    u64 a_f0[4], a_g0[4], a_f1[4], a_g1[4];
#pragma unroll
    for (int q = 0; q < 4; q++) { a_f0[q]=0; a_g0[q]=0; a_f1[q]=0; a_g1[q]=0; }
#pragma unroll 8
    for (int ci = 0; ci < C; ci++) {
        float2 wf0 = *(const float2*)&s_fw[(c0 * C + ci) * 2];
        float2 wf1 = *(const float2*)&s_fw[(c1 * C + ci) * 2];
        float2 wg0 = *(const float2*)&s_gw[(c0 * C + ci) * 2];
        float2 wg1 = *(const float2*)&s_gw[(c1 * C + ci) * 2];
        u64 wf0x, wf0y, wg0x, wg0y, wf1x, wf1y, wg1x, wg1y;
        PACK2(wf0x, wf0.x, wf0.x);  PACK2(wf0y, wf0.y, wf0.y);
        PACK2(wg0x, wg0.x, wg0.x);  PACK2(wg0y, wg0.y, wg0.y);
        PACK2(wf1x, wf1.x, wf1.x);  PACK2(wf1y, wf1.y, wf1.y);
        PACK2(wg1x, wg1.x, wg1.x);  PACK2(wg1y, wg1.y, wg1.y);
        const u64* dp = (const u64*)&xd[ci * LT + ttb];
        const u64* sp = (const u64*)&xs[ci * LT + ttb];
#pragma unroll
        for (int q = 0; q < 4; q++) {
            u64 dv = dp[q], sv = sp[q];
            FMA2(a_f0[q], wf0x, dv);  FMA2(a_f0[q], wf0y, sv);
            FMA2(a_g0[q], wg0x, dv);  FMA2(a_g0[q], wg0y, sv);
            FMA2(a_f1[q], wf1x, dv);  FMA2(a_f1[q], wf1y, sv);
            FMA2(a_g1[q], wg1x, dv);  FMA2(a_g1[q], wg1y, sv);
        }
    }
    float af0[8], ag0[8], af1[8], ag1[8];
#pragma unroll
    for (int q = 0; q < 4; q++) {
        UNPACK2(af0[2*q], af0[2*q+1], a_f0[q]);
        UNPACK2(ag0[2*q], ag0[2*q+1], a_g0[q]);
        UNPACK2(af1[2*q], af1[2*q+1], a_f1[q]);
        UNPACK2(ag1[2*q], ag1[2*q+1], a_g1[q]);
    }
    float hv0[8], hv1[8];
#pragma unroll
    for (int q = 0; q < 8; q++) {
        hv0[q] = gate_hw(af0[q], ag0[q]);
        hv1[q] = gate_hw(af1[q], ag1[q]);
    }
#pragma unroll
    for (int q = 0; q < 8; q++) {
        hs[c0 * LT + ttb + q] = hv0[q];
        hs[c1 * LT + ttb + q] = hv1[q];
    }
    {
        // global h store only where skip reads it (t >= OFF); t < T always.
        // tb is 8-aligned -> 32B aligned addresses -> STG.128 legal.
        float* h0 = hout + (size_t)b * C * T + (size_t)c0 * T;
        float* h1 = hout + (size_t)b * C * T + (size_t)c1 * T;
        int tb = t0 + ttb;
        if (tb >= OFF) {
            *(float4*)&h0[tb]     = *(float4*)&hv0[0];
            *(float4*)&h0[tb + 4] = *(float4*)&hv0[4];
            *(float4*)&h1[tb]     = *(float4*)&hv1[0];
            *(float4*)&h1[tb + 4] = *(float4*)&hv1[4];
        } else if (tb + 7 >= OFF) {
#pragma unroll
            for (int q = 0; q < 8; q++) {
                int t = tb + q;
                if (t >= OFF) { h0[t] = hv0[q]; h1[t] = hv1[q]; }
            }
        }
    }
    __syncthreads();

    // ---- phase 2: residual 1x1 conv; thread = (group of 16 out-ch, 1 t)
    {
        int grp = tid >> 7, tloc = tid & (LT - 1);
        float hreg[C];
#pragma unroll
        for (int ci = 0; ci < C; ci++) hreg[ci] = hs[ci * LT + tloc];
        int tg = t0 + tloc;
        if (tg >= lo) {
            float* xob = xout + (size_t)b * C * T;
#pragma unroll
            for (int k = 0; k < 16; k++) {
                int co = grp * 16 + k;
                float acc = 0.f;
#pragma unroll
                for (int ci = 0; ci < C; ci++) acc += s_rw[co * C + ci] * hreg[ci];
                xob[co * T + tg] = acc + xs[co * LT + tloc];
            }
        }
    }
}

// ---------------------------------------------------------------------------
// Fused skip reduction (coalesced g_swT weights), f32x2-packed.
// unroll 8 -> 8 weight loads in flight; 8x16 FMA2 x 2cyc = 256 cyc > L2 latency.
// ---------------------------------------------------------------------------
__global__ __launch_bounds__(256) void skip_kernel() {
    extern __shared__ float hs2[];                    // [NL*C][TT2]
    int b = blockIdx.y, j0 = blockIdx.x * TT2, tid = threadIdx.x;

    for (int i = tid; i < NL * C * TT2; i += 256) {
        int k = i >> 5, tt = i & (TT2 - 1);
        int j = j0 + tt;
        float v = 0.f;
        if (j < TOUT) {
            int layer = k >> 5, cc = k & 31;
            v = g_h[(((size_t)layer * B + b) * C + cc) * T + OFF + j];
        }
        hs2[i] = v;
    }
    __syncthreads();

    int co = tid;
    u64 acc2[TT2 / 2];
#pragma unroll
    for (int q = 0; q < TT2 / 2; q++) acc2[q] = 0;

    const float* wT = g_swT + co;                     // lane-coalesced base
#pragma unroll 8
    for (int kk = 0; kk < NL * C; kk++) {             // kk = layer*C + c2
        float w = __ldg(&wT[(size_t)kk * NCH]);
        u64 w2;  PACK2(w2, w, w);
        const u64* hp = (const u64*)&hs2[kk * TT2];
#pragma unroll
        for (int q = 0; q < TT2 / 2; q++) FMA2(acc2[q], w2, hp[q]);
    }
    float* so = g_skip + ((size_t)b * NCH + co) * TOUT;
#pragma unroll
    for (int q = 0; q < TT2 / 2; q++) {
        float lo, hi;
        UNPACK2(lo, hi, acc2[q]);
        int j = j0 + 2 * q;
        if (j     < TOUT) so[j]     = fmaxf(lo, 0.f);
        if (j + 1 < TOUT) so[j + 1] = fmaxf(hi, 0.f);
    }
}

// ---------------------------------------------------------------------------
// Head (coalesced g_w1T/g_w2T), f32x2-packed, TT3=32 (2x weight amortization),
// unroll-8 prefetch. Dynamic smem: 2 x 32KB.
// ---------------------------------------------------------------------------
__global__ __launch_bounds__(256) void head_kernel(
    const float* __restrict__ b1, const float* __restrict__ b2,
    float* __restrict__ out) {
    extern __shared__ float sm2[];
    float* ss = sm2;                                  // [NCH][TT3] relu(skip)
    float* as = sm2 + NCH * TT3;                      // [NCH][TT3] hidden
    int b = blockIdx.y, j0 = blockIdx.x * TT3, tid = threadIdx.x;

    for (int i = tid; i < NCH * TT3; i += 256) {
        int k = i >> 5, tt = i & (TT3 - 1);
        int j = j0 + tt;
        ss[i] = (j < TOUT) ? g_skip[((size_t)b * NCH + k) * TOUT + j] : 0.f;
    }
    __syncthreads();

    int co = tid;
    u64 acc2[TT3 / 2];
#pragma unroll
    for (int q = 0; q < TT3 / 2; q++) acc2[q] = 0;
    const float* w1c = g_w1T + co;
#pragma unroll 8
    for (int k = 0; k < NCH; k++) {
        float w = __ldg(&w1c[(size_t)k * NCH]);
        u64 w2;  PACK2(w2, w, w);
        const u64* sp = (const u64*)&ss[k * TT3];
#pragma unroll
        for (int q = 0; q < TT3 / 2; q++) FMA2(acc2[q], w2, sp[q]);
    }
    float bb1 = b1[co];
#pragma unroll
    for (int q = 0; q < TT3 / 2; q++) {
        float lo, hi;
        UNPACK2(lo, hi, acc2[q]);
        as[co * TT3 + 2 * q]     = fmaxf(lo + bb1, 0.f);
        as[co * TT3 + 2 * q + 1] = fmaxf(hi + bb1, 0.f);
    }
    __syncthreads();

#pragma unroll
    for (int q = 0; q < TT3 / 2; q++) acc2[q] = 0;
    const float* w2c = g_w2T + co;
#pragma unroll 8
    for (int k = 0; k < NCH; k++) {
        float w = __ldg(&w2c[(size_t)k * NCH]);
        u64 w2;  PACK2(w2, w, w);
        const u64* sp = (const u64*)&as[k * TT3];
#pragma unroll
        for (int q = 0; q < TT3 / 2; q++) FMA2(acc2[q], w2, sp[q]);
    }
    float bb2 = b2[co];
    float* op = out + ((size_t)b * NCH + co) * TOUT;
#pragma unroll
    for (int q = 0; q < TT3 / 2; q++) {
        float lo, hi;
        UNPACK2(lo, hi, acc2[q]);
        int j = j0 + 2 * q;
        if (j     < TOUT) op[j]     = lo + bb2;
        if (j + 1 < TOUT) op[j + 1] = hi + bb2;
    }
}

// ---------------------------------------------------------------------------
extern "C" void kernel_launch(void* const* d_in, const int* in_sizes, int n_in,
                              void* d_out, int out_size) {
    const float* y   = (const float*)d_in[0];
    const float* cw  = (const float*)d_in[1];
    const float* cb  = (const float*)d_in[2];
    const float* fw  = (const float*)d_in[3];
    const float* gw  = (const float*)d_in[4];
    const float* rw  = (const float*)d_in[5];
    const float* sw  = (const float*)d_in[6];
    const float* e1w = (const float*)d_in[7];
    const float* e1b = (const float*)d_in[8];
    const float* e2w = (const float*)d_in[9];
    const float* e2b = (const float*)d_in[10];
    float* out = (float*)d_out;

    transpose_sw_kernel<<<(NL * NCH * C + 255) / 256, 256>>>(sw);
    transpose_w_kernel<<<(NCH * NCH + 255) / 256, 256>>>(e1w, 0);
    transpose_w_kernel<<<(NCH * NCH + 255) / 256, 256>>>(e2w, 1);

    causal_kernel<<<(B * C * T + 255) / 256, 256>>>(y, cw, cb);

    const int lyr_smem = (5120 + 3 * C * LT) * 4;     // 69,632 B
    cudaFuncSetAttribute(layer_kernel, cudaFuncAttributeMaxDynamicSharedMemorySize,
                         lyr_smem);

    int lin = 0;
    for (int i = 0; i < NL; i++) {
        int d  = 1 << (i % 10);
        int lo = lin + d;                  // first valid output time index
        int tb = lo & ~(LT - 1);
        int tiles = (T - tb + LT - 1) / LT;
        dim3 grid(tiles, B);
        layer_kernel<<<grid, 256, lyr_smem>>>(fw + (size_t)i * C * C * 2,
                                              gw + (size_t)i * C * C * 2,
                                              rw + (size_t)i * C * C,
                                              i, i & 1, d, lo);
        lin = lo;
    }

    cudaFuncSetAttribute(skip_kernel, cudaFuncAttributeMaxDynamicSharedMemorySize,
                         NL * C * TT2 * 4);
    dim3 gs((TOUT + TT2 - 1) / TT2, B);
    skip_kernel<<<gs, 256, NL * C * TT2 * 4>>>();

    const int head_smem = 2 * NCH * TT3 * 4;          // 65,536 B
    cudaFuncSetAttribute(head_kernel, cudaFuncAttributeMaxDynamicSharedMemorySize,
                         head_smem);
    dim3 gh((TOUT + TT3 - 1) / TT3, B);
    head_kernel<<<gh, 256, head_smem>>>(e1b, e2b, out);
}

// round 15
// speedup vs baseline: 1.1875x; 1.0233x over previous
#include <cuda_runtime.h>

#define B    16
#define C    32
#define T    16384
#define NL   30
#define OFF  3069
#define TOUT (T - OFF)   // 13315
#define NCH  256
#define TT2  32
#define TT3  32
#define LT   128         // layer time tile
#define KH   480         // skip kernel k-rows per smem stage (2 stages of 480)

typedef unsigned long long u64;

// Packed f32x2 helpers (Blackwell): 2 fp32 FMAs per issue slot, .rn rounding
#define PACK2(dst, lo, hi) \
    asm("mov.b64 %0, {%1, %2};" : "=l"(dst) : "f"(lo), "f"(hi))
#define UNPACK2(lo, hi, src) \
    asm("mov.b64 {%0, %1}, %2;" : "=f"(lo), "=f"(hi) : "l"(src))
#define FMA2(acc, a, b) \
    asm("fma.rn.f32x2 %0, %1, %2, %0;" : "+l"(acc) : "l"(a), "l"(b))

// HW tanh (MUFU.TANH, 1 instruction). sig(g) = 0.5*(1+tanh(g/2)).
__device__ __forceinline__ float tanh_hw(float x) {
    float r;
    asm("tanh.approx.f32 %0, %1;" : "=f"(r) : "f"(x));
    return r;
}
__device__ __forceinline__ float gate_hw(float f, float g) {
    return tanh_hw(f) * (0.5f * tanh_hw(0.5f * g) + 0.5f);
}

// Scratch (device globals). CRITICAL RULE (learned R3-R12): these symbols must
// NEVER be passed as kernel launch arguments from host code — host-side &sym is
// a host shadow address; on-device deref triggers HMM migration (512MB device
// mem delta -> harness rule trip). Reference them ONLY inside device code.
__device__ float g_x[2][(size_t)B * C * T];          //  64 MB ping-pong residual stream
__device__ float g_h[(size_t)NL * B * C * T];        // ~1  GB per-layer gated outputs
__device__ float g_skip[(size_t)B * NCH * TOUT];     // 218 MB relu(skip-sum)
__device__ float g_swT[(size_t)NL * C * NCH];        // skip_w transposed [l*C+c][co]
__device__ float g_w1T[(size_t)NCH * NCH];           // end1_w transposed [k][co]
__device__ float g_w2T[(size_t)NCH * NCH];           // end2_w transposed [k][co]

// ---------------------------------------------------------------------------
// Weight transposes (one-shot, trivial)
// ---------------------------------------------------------------------------
__global__ void transpose_sw_kernel(const float* __restrict__ sw) {
    int idx = blockIdx.x * 256 + threadIdx.x;        // over NL*NCH*C, sw[l][co][c]
    if (idx >= NL * NCH * C) return;
    int c  = idx & 31;
    int co = (idx >> 5) & 255;
    int l  = idx >> 13;
    g_swT[((size_t)l * C + c) * NCH + co] = sw[idx];
}

__global__ void transpose_w_kernel(const float* __restrict__ w, int which) {
    int idx = blockIdx.x * 256 + threadIdx.x;        // over NCH*NCH, w[co][k]
    if (idx >= NCH * NCH) return;
    int k  = idx & 255;
    int co = idx >> 8;
    float* dst = which ? g_w2T : g_w1T;
    dst[(size_t)k * NCH + co] = w[idx];
}

// ---------------------------------------------------------------------------
// 1x1 causal conv: x0[b][c][t] = cw[c]*y[b][t] + cb[c]
// ---------------------------------------------------------------------------
__global__ void causal_kernel(const float* __restrict__ y,
                              const float* __restrict__ cw,
                              const float* __restrict__ cb) {
    int idx = blockIdx.x * 256 + threadIdx.x;         // over B*C*T
    if (idx >= B * C * T) return;
    int t = idx & (T - 1);
    int c = (idx >> 14) & 31;
    int b = idx >> 19;
    g_x[0][idx] = cw[c] * y[b * T + t] + cb[c];
}

// ---------------------------------------------------------------------------
// One WaveNet layer, 128-t tile, 256 threads.
// Phase 1: thread = (2 out-ch, 8 t). Weights pre-packed as (w,w) u64 pairs in
// smem -> one LDS.128 per float2 weight, NO PACK2 in the inner loop.
// Phase 2: thread = (16 out-ch, 1 t), scalar.
// ---------------------------------------------------------------------------
__global__ __launch_bounds__(256) void layer_kernel(
    const float* __restrict__ fw, const float* __restrict__ gw,
    const float* __restrict__ rw, int layer, int ping, int d, int lo) {
    extern __shared__ float sm[];
    u64*   s_fw2 = (u64*)sm;                          // [C*C*2] u64 = 16KB
    u64*   s_gw2 = (u64*)(sm + 4096);                 // 16KB
    float* s_rw  = sm + 8192;                         // 4KB
    float* xs    = sm + 9216;                         // C*LT (16KB)
    float* xd    = xs + C * LT;                       // 16KB
    float* hs    = xd + C * LT;                       // 16KB  -> total 84KB

    const float* xin  = g_x[ping];
    float*       xout = g_x[ping ^ 1];
    float*       hout = g_h + (size_t)layer * B * C * T;

    int b   = blockIdx.y;
    int tid = threadIdx.x;
    int t0  = (lo & ~(LT - 1)) + blockIdx.x * LT;     // 128-aligned; t0 <= T-128

    // Stage weights: duplicate each scalar into a packed (w,w) u64.
    // Layout: pair index i = c*C+ci holds [2i]=(w.x,w.x), [2i+1]=(w.y,w.y)
    // so &s_fw2[2i] is 16B-aligned -> LDS.128 fetches both.
    for (int i = tid; i < C * C; i += 256) {
        float2 wf = ((const float2*)fw)[i];
        float2 wg = ((const float2*)gw)[i];
        u64 p;
        PACK2(p, wf.x, wf.x);  s_fw2[2 * i]     = p;
        PACK2(p, wf.y, wf.y);  s_fw2[2 * i + 1] = p;
        PACK2(p, wg.x, wg.x);  s_gw2[2 * i]     = p;
        PACK2(p, wg.y, wg.y);  s_gw2[2 * i + 1] = p;
    }
    for (int i = tid; i < C * C; i += 256) s_rw[i] = rw[i];

    const float* xb = xin + (size_t)b * C * T;
    for (int i = tid; i < C * LT; i += 256) {
        int c = i >> 7, tt = i & (LT - 1);
        int t = t0 + tt;
        bool v = (t >= lo);                           // t < T always (t0 <= T-128)
        xs[i] = v ? xb[c * T + t]     : 0.f;
        xd[i] = v ? xb[c * T + t - d] : 0.f;
    }
    __syncthreads();

    // ---- phase 1: thread = (channels c0,c1) x (8 time steps), packed f32x2
    int cp  = tid >> 4;                               // 0..15
    int c0  = cp * 2, c1 = c0 + 1;
    int ttb = (tid & 15) * 8;
    u64 a_f0[4], a_g0[4], a_f1[4], a_g1[4];
#pragma unroll
    for (int q = 0; q < 4; q++) { a_f0[q]=0; a_g0[q]=0; a_f1[q]=0; a_g1[q]=0; }
#pragma unroll 8
    for (int ci = 0; ci < C; ci++) {
        ulonglong2 wf0 = *(const ulonglong2*)&s_fw2[(c0 * C + ci) * 2];
        ulonglong2 wf1 = *(const ulonglong2*)&s_fw2[(c1 * C + ci) * 2];
        ulonglong2 wg0 = *(const ulonglong2*)&s_gw2[(c0 * C + ci) * 2];
        ulonglong2 wg1 = *(const ulonglong2*)&s_gw2[(c1 * C + ci) * 2];
        const u64* dp = (const u64*)&xd[ci * LT + ttb];
        const u64* sp = (const u64*)&xs[ci * LT + ttb];
#pragma unroll
        for (int q = 0; q < 4; q++) {
            u64 dv = dp[q], sv = sp[q];
            FMA2(a_f0[q], wf0.x, dv);  FMA2(a_f0[q], wf0.y, sv);
            FMA2(a_g0[q], wg0.x, dv);  FMA2(a_g0[q], wg0.y, sv);
            FMA2(a_f1[q], wf1.x, dv);  FMA2(a_f1[q], wf1.y, sv);
            FMA2(a_g1[q], wg1.x, dv);  FMA2(a_g1[q], wg1.y, sv);
        }
    }
    float af0[8], ag0[8], af1[8], ag1[8];
#pragma unroll
    for (int q = 0; q < 4; q++) {
        UNPACK2(af0[2*q], af0[2*q+1], a_f0[q]);
        UNPACK2(ag0[2*q], ag0[2*q+1], a_g0[q]);
        UNPACK2(af1[2*q], af1[2*q+1], a_f1[q]);
        UNPACK2(ag1[2*q], ag1[2*q+1], a_g1[q]);
    }
    float hv0[8], hv1[8];
#pragma unroll
    for (int q = 0; q < 8; q++) {
        hv0[q] = gate_hw(af0[q], ag0[q]);
        hv1[q] = gate_hw(af1[q], ag1[q]);
    }
#pragma unroll
    for (int q = 0; q < 8; q++) {
        hs[c0 * LT + ttb + q] = hv0[q];
        hs[c1 * LT + ttb + q] = hv1[q];
    }
    {
        // global h store only where skip reads it (t >= OFF); t < T always.
        float* h0 = hout + (size_t)b * C * T + (size_t)c0 * T;
        float* h1 = hout + (size_t)b * C * T + (size_t)c1 * T;
        int tb = t0 + ttb;
        if (tb >= OFF) {
            *(float4*)&h0[tb]     = *(float4*)&hv0[0];
            *(float4*)&h0[tb + 4] = *(float4*)&hv0[4];
            *(float4*)&h1[tb]     = *(float4*)&hv1[0];
            *(float4*)&h1[tb + 4] = *(float4*)&hv1[4];
        } else if (tb + 7 >= OFF) {
#pragma unroll
            for (int q = 0; q < 8; q++) {
                int t = tb + q;
                if (t >= OFF) { h0[t] = hv0[q]; h1[t] = hv1[q]; }
            }
        }
    }
    __syncthreads();

    // ---- phase 2: residual 1x1 conv; thread = (group of 16 out-ch, 1 t)
    {
        int grp = tid >> 7, tloc = tid & (LT - 1);
        float hreg[C];
#pragma unroll
        for (int ci = 0; ci < C; ci++) hreg[ci] = hs[ci * LT + tloc];
        int tg = t0 + tloc;
        if (tg >= lo) {
            float* xob = xout + (size_t)b * C * T;
#pragma unroll
            for (int k = 0; k < 16; k++) {
                int co = grp * 16 + k;
                float acc = 0.f;
#pragma unroll
                for (int ci = 0; ci < C; ci++) acc += s_rw[co * C + ci] * hreg[ci];
                xob[co * T + tg] = acc + xs[co * LT + tloc];
            }
        }
    }
}

// ---------------------------------------------------------------------------
// Fused skip reduction, TWO-STAGE smem (KH=480 rows x TT2) -> 60KB -> 3 blk/SM.
// ---------------------------------------------------------------------------
__global__ __launch_bounds__(256) void skip_kernel() {
    extern __shared__ float hs2[];                    // [KH][TT2] = 60KB
    int b = blockIdx.y, j0 = blockIdx.x * TT2, tid = threadIdx.x;

    int co = tid;
    u64 acc2[TT2 / 2];
#pragma unroll
    for (int q = 0; q < TT2 / 2; q++) acc2[q] = 0;

    const float* wT = g_swT + co;                     // lane-coalesced base

    for (int half = 0; half < 2; half++) {
        // stage rows [half*KH, half*KH+KH)
        for (int i = tid; i < KH * TT2; i += 256) {
            int k = half * KH + (i >> 5);
            int tt = i & (TT2 - 1);
            int j = j0 + tt;
            float v = 0.f;
            if (j < TOUT) {
                int layer = k >> 5, cc = k & 31;
                v = g_h[(((size_t)layer * B + b) * C + cc) * T + OFF + j];
            }
            hs2[i] = v;
        }
        __syncthreads();

        const float* wTh = wT + (size_t)half * KH * NCH;
#pragma unroll 8
        for (int kk = 0; kk < KH; kk++) {
            float w = __ldg(&wTh[(size_t)kk * NCH]);
            u64 w2;  PACK2(w2, w, w);
            const u64* hp = (const u64*)&hs2[kk * TT2];
#pragma unroll
            for (int q = 0; q < TT2 / 2; q++) FMA2(acc2[q], w2, hp[q]);
        }
        __syncthreads();
    }

    float* so = g_skip + ((size_t)b * NCH + co) * TOUT;
#pragma unroll
    for (int q = 0; q < TT2 / 2; q++) {
        float lo, hi;
        UNPACK2(lo, hi, acc2[q]);
        int j = j0 + 2 * q;
        if (j     < TOUT) so[j]     = fmaxf(lo, 0.f);
        if (j + 1 < TOUT) so[j + 1] = fmaxf(hi, 0.f);
    }
}

// ---------------------------------------------------------------------------
// Head (coalesced g_w1T/g_w2T), f32x2-packed, TT3=32, unroll-8 prefetch.
// ---------------------------------------------------------------------------
__global__ __launch_bounds__(256) void head_kernel(
    const float* __restrict__ b1, const float* __restrict__ b2,
    float* __restrict__ out) {
    extern __shared__ float sm2[];
    float* ss = sm2;                                  // [NCH][TT3] relu(skip)
    float* as = sm2 + NCH * TT3;                      // [NCH][TT3] hidden
    int b = blockIdx.y, j0 = blockIdx.x * TT3, tid = threadIdx.x;

    for (int i = tid; i < NCH * TT3; i += 256) {
        int k = i >> 5, tt = i & (TT3 - 1);
        int j = j0 + tt;
        ss[i] = (j < TOUT) ? g_skip[((size_t)b * NCH + k) * TOUT + j] : 0.f;
    }
    __syncthreads();

    int co = tid;
    u64 acc2[TT3 / 2];
#pragma unroll
    for (int q = 0; q < TT3 / 2; q++) acc2[q] = 0;
    const float* w1c = g_w1T + co;
#pragma unroll 8
    for (int k = 0; k < NCH; k++) {
        float w = __ldg(&w1c[(size_t)k * NCH]);
        u64 w2;  PACK2(w2, w, w);
        const u64* sp = (const u64*)&ss[k * TT3];
#pragma unroll
        for (int q = 0; q < TT3 / 2; q++) FMA2(acc2[q], w2, sp[q]);
    }
    float bb1 = b1[co];
#pragma unroll
    for (int q = 0; q < TT3 / 2; q++) {
        float lo, hi;
        UNPACK2(lo, hi, acc2[q]);
        as[co * TT3 + 2 * q]     = fmaxf(lo + bb1, 0.f);
        as[co * TT3 + 2 * q + 1] = fmaxf(hi + bb1, 0.f);
    }
    __syncthreads();

#pragma unroll
    for (int q = 0; q < TT3 / 2; q++) acc2[q] = 0;
    const float* w2c = g_w2T + co;
#pragma unroll 8
    for (int k = 0; k < NCH; k++) {
        float w = __ldg(&w2c[(size_t)k * NCH]);
        u64 w2;  PACK2(w2, w, w);
        const u64* sp = (const u64*)&as[k * TT3];
#pragma unroll
        for (int q = 0; q < TT3 / 2; q++) FMA2(acc2[q], w2, sp[q]);
    }
    float bb2 = b2[co];
    float* op = out + ((size_t)b * NCH + co) * TOUT;
#pragma unroll
    for (int q = 0; q < TT3 / 2; q++) {
        float lo, hi;
        UNPACK2(lo, hi, acc2[q]);
        int j = j0 + 2 * q;
        if (j     < TOUT) op[j]     = lo + bb2;
        if (j + 1 < TOUT) op[j + 1] = hi + bb2;
    }
}

// ---------------------------------------------------------------------------
extern "C" void kernel_launch(void* const* d_in, const int* in_sizes, int n_in,
                              void* d_out, int out_size) {
    const float* y   = (const float*)d_in[0];
    const float* cw  = (const float*)d_in[1];
    const float* cb  = (const float*)d_in[2];
    const float* fw  = (const float*)d_in[3];
    const float* gw  = (const float*)d_in[4];
    const float* rw  = (const float*)d_in[5];
    const float* sw  = (const float*)d_in[6];
    const float* e1w = (const float*)d_in[7];
    const float* e1b = (const float*)d_in[8];
    const float* e2w = (const float*)d_in[9];
    const float* e2b = (const float*)d_in[10];
    float* out = (float*)d_out;

    transpose_sw_kernel<<<(NL * NCH * C + 255) / 256, 256>>>(sw);
    transpose_w_kernel<<<(NCH * NCH + 255) / 256, 256>>>(e1w, 0);
    transpose_w_kernel<<<(NCH * NCH + 255) / 256, 256>>>(e2w, 1);

    causal_kernel<<<(B * C * T + 255) / 256, 256>>>(y, cw, cb);

    const int lyr_smem = (9216 + 3 * C * LT) * 4;     // 86,016 B
    cudaFuncSetAttribute(layer_kernel, cudaFuncAttributeMaxDynamicSharedMemorySize,
                         lyr_smem);

    int lin = 0;
    for (int i = 0; i < NL; i++) {
        int d  = 1 << (i % 10);
        int lo = lin + d;                  // first valid output time index
        int tb = lo & ~(LT - 1);
        int tiles = (T - tb + LT - 1) / LT;
        dim3 grid(tiles, B);
        layer_kernel<<<grid, 256, lyr_smem>>>(fw + (size_t)i * C * C * 2,
                                              gw + (size_t)i * C * C * 2,
                                              rw + (size_t)i * C * C,
                                              i, i & 1, d, lo);
        lin = lo;
    }

    const int skip_smem = KH * TT2 * 4;               // 61,440 B
    cudaFuncSetAttribute(skip_kernel, cudaFuncAttributeMaxDynamicSharedMemorySize,
                         skip_smem);
    dim3 gs((TOUT + TT2 - 1) / TT2, B);
    skip_kernel<<<gs, 256, skip_smem>>>();

    const int head_smem = 2 * NCH * TT3 * 4;          // 65,536 B
    cudaFuncSetAttribute(head_kernel, cudaFuncAttributeMaxDynamicSharedMemorySize,
                         head_smem);
    dim3 gh((TOUT + TT3 - 1) / TT3, B);
    head_kernel<<<gh, 256, head_smem>>>(e1b, e2b, out);
}

// round 16
// speedup vs baseline: 1.2234x; 1.0302x over previous
#include <cuda_runtime.h>

#define B    16
#define C    32
#define T    16384
#define NL   30
#define OFF  3069
#define TOUT (T - OFF)   // 13315
#define NCH  256
#define TT2  32
#define TT3  32
#define LT   128         // layer time tile
#define KH   480         // skip kernel k-rows per smem stage (2 stages of 480)

typedef unsigned long long u64;

// Packed f32x2 helpers (Blackwell): 2 fp32 FMAs per issue slot, .rn rounding
#define PACK2(dst, lo, hi) \
    asm("mov.b64 %0, {%1, %2};" : "=l"(dst) : "f"(lo), "f"(hi))
#define UNPACK2(lo, hi, src) \
    asm("mov.b64 {%0, %1}, %2;" : "=f"(lo), "=f"(hi) : "l"(src))
#define FMA2(acc, a, b) \
    asm("fma.rn.f32x2 %0, %1, %2, %0;" : "+l"(acc) : "l"(a), "l"(b))
#define ADD2(dst, a, b) \
    asm("add.rn.f32x2 %0, %1, %2;" : "=l"(dst) : "l"(a), "l"(b))

// HW tanh (MUFU.TANH, 1 instruction). sig(g) = 0.5*(1+tanh(g/2)).
__device__ __forceinline__ float tanh_hw(float x) {
    float r;
    asm("tanh.approx.f32 %0, %1;" : "=f"(r) : "f"(x));
    return r;
}
__device__ __forceinline__ float gate_hw(float f, float g) {
    return tanh_hw(f) * (0.5f * tanh_hw(0.5f * g) + 0.5f);
}

// Scratch (device globals). CRITICAL RULE (learned R3-R12): these symbols must
// NEVER be passed as kernel launch arguments from host code — host-side &sym is
// a host shadow address; on-device deref triggers HMM migration (512MB device
// mem delta -> harness rule trip). Reference them ONLY inside device code.
__device__ float g_x[2][(size_t)B * C * T];          //  64 MB ping-pong residual stream
__device__ float g_h[(size_t)NL * B * C * T];        // ~1  GB per-layer gated outputs
__device__ float g_skip[(size_t)B * NCH * TOUT];     // 218 MB relu(skip-sum)
__device__ float g_swT[(size_t)NL * C * NCH];        // skip_w transposed [l*C+c][co]
__device__ float g_w1T[(size_t)NCH * NCH];           // end1_w transposed [k][co]
__device__ float g_w2T[(size_t)NCH * NCH];           // end2_w transposed [k][co]

// ---------------------------------------------------------------------------
// Weight transposes (one-shot, trivial)
// ---------------------------------------------------------------------------
__global__ void transpose_sw_kernel(const float* __restrict__ sw) {
    int idx = blockIdx.x * 256 + threadIdx.x;        // over NL*NCH*C, sw[l][co][c]
    if (idx >= NL * NCH * C) return;
    int c  = idx & 31;
    int co = (idx >> 5) & 255;
    int l  = idx >> 13;
    g_swT[((size_t)l * C + c) * NCH + co] = sw[idx];
}

__global__ void transpose_w_kernel(const float* __restrict__ w, int which) {
    int idx = blockIdx.x * 256 + threadIdx.x;        // over NCH*NCH, w[co][k]
    if (idx >= NCH * NCH) return;
    int k  = idx & 255;
    int co = idx >> 8;
    float* dst = which ? g_w2T : g_w1T;
    dst[(size_t)k * NCH + co] = w[idx];
}

// ---------------------------------------------------------------------------
// 1x1 causal conv: x0[b][c][t] = cw[c]*y[b][t] + cb[c]
// ---------------------------------------------------------------------------
__global__ void causal_kernel(const float* __restrict__ y,
                              const float* __restrict__ cw,
                              const float* __restrict__ cb) {
    int idx = blockIdx.x * 256 + threadIdx.x;         // over B*C*T
    if (idx >= B * C * T) return;
    int t = idx & (T - 1);
    int c = (idx >> 14) & 31;
    int b = idx >> 19;
    g_x[0][idx] = cw[c] * y[b * T + t] + cb[c];
}

// ---------------------------------------------------------------------------
// One WaveNet layer, 128-t tile, 256 threads.
// Phase 1: thread = (2 out-ch, 8 t). Weights pre-packed (w,w) u64 in smem.
// Phase 2: thread = (8 out-ch, 2 packed t), FMA2 + ADD2, packed rw weights.
// ---------------------------------------------------------------------------
__global__ __launch_bounds__(256) void layer_kernel(
    const float* __restrict__ fw, const float* __restrict__ gw,
    const float* __restrict__ rw, int layer, int ping, int d, int lo) {
    extern __shared__ float sm[];
    u64*   s_fw2 = (u64*)sm;                          // [C*C*2] u64 = 16KB
    u64*   s_gw2 = (u64*)(sm + 4096);                 // 16KB
    u64*   s_rw2 = (u64*)(sm + 8192);                 // [C*C] u64 = 8KB
    float* xs    = sm + 10240;                        // C*LT (16KB)
    float* xd    = xs + C * LT;                       // 16KB
    float* hs    = xd + C * LT;                       // 16KB -> total 88KB

    const float* xin  = g_x[ping];
    float*       xout = g_x[ping ^ 1];
    float*       hout = g_h + (size_t)layer * B * C * T;

    int b   = blockIdx.y;
    int tid = threadIdx.x;
    int t0  = (lo & ~(LT - 1)) + blockIdx.x * LT;     // 128-aligned; t0 <= T-128

    // Stage weights: duplicate each scalar into a packed (w,w) u64.
    for (int i = tid; i < C * C; i += 256) {
        float2 wf = ((const float2*)fw)[i];
        float2 wg = ((const float2*)gw)[i];
        float  wr = rw[i];
        u64 p;
        PACK2(p, wf.x, wf.x);  s_fw2[2 * i]     = p;
        PACK2(p, wf.y, wf.y);  s_fw2[2 * i + 1] = p;
        PACK2(p, wg.x, wg.x);  s_gw2[2 * i]     = p;
        PACK2(p, wg.y, wg.y);  s_gw2[2 * i + 1] = p;
        PACK2(p, wr, wr);      s_rw2[i]         = p;
    }

    const float* xb = xin + (size_t)b * C * T;
    for (int i = tid; i < C * LT; i += 256) {
        int c = i >> 7, tt = i & (LT - 1);
        int t = t0 + tt;
        bool v = (t >= lo);                           // t < T always (t0 <= T-128)
        xs[i] = v ? xb[c * T + t]     : 0.f;
        xd[i] = v ? xb[c * T + t - d] : 0.f;
    }
    __syncthreads();

    // ---- phase 1: thread = (channels c0,c1) x (8 time steps), packed f32x2
    int cp  = tid >> 4;                               // 0..15
    int c0  = cp * 2, c1 = c0 + 1;
    int ttb = (tid & 15) * 8;
    u64 a_f0[4], a_g0[4], a_f1[4], a_g1[4];
#pragma unroll
    for (int q = 0; q < 4; q++) { a_f0[q]=0; a_g0[q]=0; a_f1[q]=0; a_g1[q]=0; }
#pragma unroll 8
    for (int ci = 0; ci < C; ci++) {
        ulonglong2 wf0 = *(const ulonglong2*)&s_fw2[(c0 * C + ci) * 2];
        ulonglong2 wf1 = *(const ulonglong2*)&s_fw2[(c1 * C + ci) * 2];
        ulonglong2 wg0 = *(const ulonglong2*)&s_gw2[(c0 * C + ci) * 2];
        ulonglong2 wg1 = *(const ulonglong2*)&s_gw2[(c1 * C + ci) * 2];
        const u64* dp = (const u64*)&xd[ci * LT + ttb];
        const u64* sp = (const u64*)&xs[ci * LT + ttb];
#pragma unroll
        for (int q = 0; q < 4; q++) {
            u64 dv = dp[q], sv = sp[q];
            FMA2(a_f0[q], wf0.x, dv);  FMA2(a_f0[q], wf0.y, sv);
            FMA2(a_g0[q], wg0.x, dv);  FMA2(a_g0[q], wg0.y, sv);
            FMA2(a_f1[q], wf1.x, dv);  FMA2(a_f1[q], wf1.y, sv);
            FMA2(a_g1[q], wg1.x, dv);  FMA2(a_g1[q], wg1.y, sv);
        }
    }
    float af0[8], ag0[8], af1[8], ag1[8];
#pragma unroll
    for (int q = 0; q < 4; q++) {
        UNPACK2(af0[2*q], af0[2*q+1], a_f0[q]);
        UNPACK2(ag0[2*q], ag0[2*q+1], a_g0[q]);
        UNPACK2(af1[2*q], af1[2*q+1], a_f1[q]);
        UNPACK2(ag1[2*q], ag1[2*q+1], a_g1[q]);
    }
    float hv0[8], hv1[8];
#pragma unroll
    for (int q = 0; q < 8; q++) {
        hv0[q] = gate_hw(af0[q], ag0[q]);
        hv1[q] = gate_hw(af1[q], ag1[q]);
    }
#pragma unroll
    for (int q = 0; q < 8; q++) {
        hs[c0 * LT + ttb + q] = hv0[q];
        hs[c1 * LT + ttb + q] = hv1[q];
    }
    {
        // global h store only where skip reads it (t >= OFF); t < T always.
        float* h0 = hout + (size_t)b * C * T + (size_t)c0 * T;
        float* h1 = hout + (size_t)b * C * T + (size_t)c1 * T;
        int tb = t0 + ttb;
        if (tb >= OFF) {
            *(float4*)&h0[tb]     = *(float4*)&hv0[0];
            *(float4*)&h0[tb + 4] = *(float4*)&hv0[4];
            *(float4*)&h1[tb]     = *(float4*)&hv1[0];
            *(float4*)&h1[tb + 4] = *(float4*)&hv1[4];
        } else if (tb + 7 >= OFF) {
#pragma unroll
            for (int q = 0; q < 8; q++) {
                int t = tb + q;
                if (t >= OFF) { h0[t] = hv0[q]; h1[t] = hv1[q]; }
            }
        }
    }
    __syncthreads();

    // ---- phase 2: residual conv; thread = (8 out-ch, 2 packed t)
    {
        int grp  = tid >> 6;                          // 0..3 -> co0 = grp*8
        int co0  = grp * 8;
        int tl2  = tid & 63;
        int tt   = tl2 * 2;                           // local t (even)
        int tg   = t0 + tt;

        u64 h2[C];
#pragma unroll
        for (int ci = 0; ci < C; ci++)
            h2[ci] = *(const u64*)&hs[ci * LT + tt];

        float* xob = xout + (size_t)b * C * T;
        bool full = (tg >= lo);
        bool part = (!full) && (tg + 1 >= lo);
#pragma unroll
        for (int k = 0; k < 8; k++) {
            int co = co0 + k;
            u64 acc2 = 0;
#pragma unroll
            for (int c2 = 0; c2 < C; c2 += 2) {
                ulonglong2 w2 = *(const ulonglong2*)&s_rw2[co * C + c2];
                FMA2(acc2, w2.x, h2[c2]);
                FMA2(acc2, w2.y, h2[c2 + 1]);
            }
            u64 xv = *(const u64*)&xs[co * LT + tt];
            u64 res;
            ADD2(res, acc2, xv);
            if (full) {
                *(u64*)&xob[co * T + tg] = res;
            } else if (part) {
                float lo_, hi_;
                UNPACK2(lo_, hi_, res);
                xob[co * T + tg + 1] = hi_;
            }
        }
    }
}

// ---------------------------------------------------------------------------
// Fused skip reduction, TWO-STAGE smem (KH=480 rows x TT2) -> 60KB -> 3 blk/SM.
// ---------------------------------------------------------------------------
__global__ __launch_bounds__(256) void skip_kernel() {
    extern __shared__ float hs2[];                    // [KH][TT2] = 60KB
    int b = blockIdx.y, j0 = blockIdx.x * TT2, tid = threadIdx.x;

    int co = tid;
    u64 acc2[TT2 / 2];
#pragma unroll
    for (int q = 0; q < TT2 / 2; q++) acc2[q] = 0;

    const float* wT = g_swT + co;                     // lane-coalesced base

    for (int half = 0; half < 2; half++) {
        for (int i = tid; i < KH * TT2; i += 256) {
            int k = half * KH + (i >> 5);
            int tt = i & (TT2 - 1);
            int j = j0 + tt;
            float v = 0.f;
            if (j < TOUT) {
                int layer = k >> 5, cc = k & 31;
                v = g_h[(((size_t)layer * B + b) * C + cc) * T + OFF + j];
            }
            hs2[i] = v;
        }
        __syncthreads();

        const float* wTh = wT + (size_t)half * KH * NCH;
#pragma unroll 8
        for (int kk = 0; kk < KH; kk++) {
            float w = __ldg(&wTh[(size_t)kk * NCH]);
            u64 w2;  PACK2(w2, w, w);
            const u64* hp = (const u64*)&hs2[kk * TT2];
#pragma unroll
            for (int q = 0; q < TT2 / 2; q++) FMA2(acc2[q], w2, hp[q]);
        }
        __syncthreads();
    }

    float* so = g_skip + ((size_t)b * NCH + co) * TOUT;
#pragma unroll
    for (int q = 0; q < TT2 / 2; q++) {
        float lo, hi;
        UNPACK2(lo, hi, acc2[q]);
        int j = j0 + 2 * q;
        if (j     < TOUT) so[j]     = fmaxf(lo, 0.f);
        if (j + 1 < TOUT) so[j + 1] = fmaxf(hi, 0.f);
    }
}

// ---------------------------------------------------------------------------
// Head (coalesced g_w1T/g_w2T), f32x2-packed, TT3=32, unroll-8 prefetch.
// ---------------------------------------------------------------------------
__global__ __launch_bounds__(256) void head_kernel(
    const float* __restrict__ b1, const float* __restrict__ b2,
    float* __restrict__ out) {
    extern __shared__ float sm2[];
    float* ss = sm2;                                  // [NCH][TT3] relu(skip)
    float* as = sm2 + NCH * TT3;                      // [NCH][TT3] hidden
    int b = blockIdx.y, j0 = blockIdx.x * TT3, tid = threadIdx.x;

    for (int i = tid; i < NCH * TT3; i += 256) {
        int k = i >> 5, tt = i & (TT3 - 1);
        int j = j0 + tt;
        ss[i] = (j < TOUT) ? g_skip[((size_t)b * NCH + k) * TOUT + j] : 0.f;
    }
    __syncthreads();

    int co = tid;
    u64 acc2[TT3 / 2];
#pragma unroll
    for (int q = 0; q < TT3 / 2; q++) acc2[q] = 0;
    const float* w1c = g_w1T + co;
#pragma unroll 8
    for (int k = 0; k < NCH; k++) {
        float w = __ldg(&w1c[(size_t)k * NCH]);
        u64 w2;  PACK2(w2, w, w);
        const u64* sp = (const u64*)&ss[k * TT3];
#pragma unroll
        for (int q = 0; q < TT3 / 2; q++) FMA2(acc2[q], w2, sp[q]);
    }
    float bb1 = b1[co];
#pragma unroll
    for (int q = 0; q < TT3 / 2; q++) {
        float lo, hi;
        UNPACK2(lo, hi, acc2[q]);
        as[co * TT3 + 2 * q]     = fmaxf(lo + bb1, 0.f);
        as[co * TT3 + 2 * q + 1] = fmaxf(hi + bb1, 0.f);
    }
    __syncthreads();

#pragma unroll
    for (int q = 0; q < TT3 / 2; q++) acc2[q] = 0;
    const float* w2c = g_w2T + co;
#pragma unroll 8
    for (int k = 0; k < NCH; k++) {
        float w = __ldg(&w2c[(size_t)k * NCH]);
        u64 w2;  PACK2(w2, w, w);
        const u64* sp = (const u64*)&as[k * TT3];
#pragma unroll
        for (int q = 0; q < TT3 / 2; q++) FMA2(acc2[q], w2, sp[q]);
    }
    float bb2 = b2[co];
    float* op = out + ((size_t)b * NCH + co) * TOUT;
#pragma unroll
    for (int q = 0; q < TT3 / 2; q++) {
        float lo, hi;
        UNPACK2(lo, hi, acc2[q]);
        int j = j0 + 2 * q;
        if (j     < TOUT) op[j]     = lo + bb2;
        if (j + 1 < TOUT) op[j + 1] = hi + bb2;
    }
}

// ---------------------------------------------------------------------------
extern "C" void kernel_launch(void* const* d_in, const int* in_sizes, int n_in,
                              void* d_out, int out_size) {
    const float* y   = (const float*)d_in[0];
    const float* cw  = (const float*)d_in[1];
    const float* cb  = (const float*)d_in[2];
    const float* fw  = (const float*)d_in[3];
    const float* gw  = (const float*)d_in[4];
    const float* rw  = (const float*)d_in[5];
    const float* sw  = (const float*)d_in[6];
    const float* e1w = (const float*)d_in[7];
    const float* e1b = (const float*)d_in[8];
    const float* e2w = (const float*)d_in[9];
    const float* e2b = (const float*)d_in[10];
    float* out = (float*)d_out;

    transpose_sw_kernel<<<(NL * NCH * C + 255) / 256, 256>>>(sw);
    transpose_w_kernel<<<(NCH * NCH + 255) / 256, 256>>>(e1w, 0);
    transpose_w_kernel<<<(NCH * NCH + 255) / 256, 256>>>(e2w, 1);

    causal_kernel<<<(B * C * T + 255) / 256, 256>>>(y, cw, cb);

    const int lyr_smem = (10240 + 3 * C * LT) * 4;    // 90,112 B
    cudaFuncSetAttribute(layer_kernel, cudaFuncAttributeMaxDynamicSharedMemorySize,
                         lyr_smem);

    int lin = 0;
    for (int i = 0; i < NL; i++) {
        int d  = 1 << (i % 10);
        int lo = lin + d;                  // first valid output time index
        int tb = lo & ~(LT - 1);
        int tiles = (T - tb + LT - 1) / LT;
        dim3 grid(tiles, B);
        layer_kernel<<<grid, 256, lyr_smem>>>(fw + (size_t)i * C * C * 2,
                                              gw + (size_t)i * C * C * 2,
                                              rw + (size_t)i * C * C,
                                              i, i & 1, d, lo);
        lin = lo;
    }

    const int skip_smem = KH * TT2 * 4;               // 61,440 B
    cudaFuncSetAttribute(skip_kernel, cudaFuncAttributeMaxDynamicSharedMemorySize,
                         skip_smem);
    dim3 gs((TOUT + TT2 - 1) / TT2, B);
    skip_kernel<<<gs, 256, skip_smem>>>();

    const int head_smem = 2 * NCH * TT3 * 4;          // 65,536 B
    cudaFuncSetAttribute(head_kernel, cudaFuncAttributeMaxDynamicSharedMemorySize,
                         head_smem);
    dim3 gh((TOUT + TT3 - 1) / TT3, B);
    head_kernel<<<gh, 256, head_smem>>>(e1b, e2b, out);
}